// round 2
// baseline (speedup 1.0000x reference)
#include <cuda_runtime.h>

#define BB 16
#define NN 25
#define WW 128
#define CH 256              // c*h
#define SS 3200             // n*w
#define BSTRIDE 819200
#define CSTRIDE 51200
#define NSTRIDE 2048

typedef unsigned long long ull;

// Scratch (device globals are zero-initialized; att never writes fully-masked
// column groups, which must read back as 0.0f in out_kernel)
__device__ float g_p[BB*CH*CH];     // softmax probabilities, 4 MB
__device__ float g_invq[BB*CH];
__device__ float g_invk[BB*CH];

__device__ __forceinline__ int row_base(int b, int t) {
    return b*BSTRIDE + (t >> 4)*CSTRIDE + (t & 15)*WW;
}
__device__ __forceinline__ void ffma2(ull& d, ull a, ull b) {
    asm("fma.rn.f32x2 %0, %1, %2, %0;" : "+l"(d) : "l"(a), "l"(b));
}
__device__ __forceinline__ ull pack2(float lo, float hi) {
    ull r; asm("mov.b64 %0, {%1, %2};" : "=l"(r) : "f"(lo), "f"(hi)); return r;
}
__device__ __forceinline__ void unpack2(ull v, float& lo, float& hi) {
    asm("mov.b64 {%0, %1}, %2;" : "=f"(lo), "=f"(hi) : "l"(v));
}

// ---------------------------------------------------------------------------
// Kernel 1: per-row L2 norms of Q and K.
// ---------------------------------------------------------------------------
__global__ __launch_bounds__(256) void norms_kernel(const float* __restrict__ q,
                                                    const float* __restrict__ k) {
    int warp = threadIdx.x >> 5, lane = threadIdx.x & 31;
    int row = blockIdx.x * 8 + warp;
    int b = row >> 8, t = row & 255;
    int base = row_base(b, t) + lane * 4;
    float sq = 0.f, sk = 0.f;
    #pragma unroll
    for (int n = 0; n < NN; ++n) {
        const float4 qa = *(const float4*)(q + base + n*NSTRIDE);
        const float4 ka = *(const float4*)(k + base + n*NSTRIDE);
        sq += qa.x*qa.x + qa.y*qa.y + qa.z*qa.z + qa.w*qa.w;
        sk += ka.x*ka.x + ka.y*ka.y + ka.z*ka.z + ka.w*ka.w;
    }
    #pragma unroll
    for (int o = 16; o; o >>= 1) {
        sq += __shfl_xor_sync(0xffffffffu, sq, o);
        sk += __shfl_xor_sync(0xffffffffu, sk, o);
    }
    if (lane == 0) {
        g_invq[row] = 1.f / fmaxf(sqrtf(sq), 1e-12f);
        g_invk[row] = 1.f / fmaxf(sqrtf(sk), 1e-12f);
    }
}

// ---------------------------------------------------------------------------
// Kernel 2: att = Qn @ Kn^T, causal mask, softmax -> g_p.
// CTA = two paired 16-row tiles (tt and 15-tt): constant work per CTA.
// Warps 0-3: tile A rows; warps 4-7: tile B rows (4 rows per warp).
// Packed f32x2 FMAs: Q duplicated-broadcast in smem, K transposed in smem.
// Columns per lane: c = 64*jj + 2*tx + {0,1}, jj<4 (64-col skippable groups).
// ---------------------------------------------------------------------------
#define SC 32
#define KSS 258     // Ks row stride (even for LDS.64 align, 8-bank STS skew)
#define QSS 66      // Qs row stride
__global__ __launch_bounds__(256) void att_kernel(const float* __restrict__ q,
                                                  const float* __restrict__ k) {
    __shared__ __align__(16) float Ks[SC*KSS];   // [s][c] transposed K
    __shared__ __align__(16) float Qs[SC*QSS];   // [s][2*r] duplicated Q
    const int tt = blockIdx.x & 7, b = blockIdx.x >> 3;
    const int a0 = tt*16, b0 = (15 - tt)*16;
    const int maxrow = b0 + 15;                  // tile B is always the heavy one
    const int ngrp = 2*(maxrow/64) + 2;          // 32-col load groups (64-col granule)
    const int tid = threadIdx.x, tx = tid & 31, wid = tid >> 5;
    const int rloc0 = (wid < 4) ? wid*4 : 16 + (wid - 4)*4;
    const int rabs0 = (wid < 4) ? a0 + wid*4 : b0 + (wid - 4)*4;
    const int njj = (rabs0 + 3)/64 + 1;          // active 64-col groups (<=4)

    // loader mapping: lsub = row/col-sub index, sl = s offset (quad)
    const int lsub = tid >> 3, sl = (tid & 7)*4;
    int kbase[8];
    #pragma unroll
    for (int g = 0; g < 8; ++g) kbase[g] = row_base(b, lsub + 32*g) + sl;
    const int qrow = (lsub < 16) ? a0 + lsub : b0 + (lsub - 16);
    const int qbase = row_base(b, qrow) + sl;

    ull acc[4][4];
    #pragma unroll
    for (int i = 0; i < 4; ++i)
        #pragma unroll
        for (int jj = 0; jj < 4; ++jj) acc[i][jj] = 0ull;

    // prefetch chunk 0
    float4 qv = *(const float4*)(q + qbase);
    float4 kv[8];
    #pragma unroll
    for (int g = 0; g < 8; ++g) if (g < ngrp) kv[g] = *(const float4*)(k + kbase[g]);

    for (int s0 = 0; s0 < SS; s0 += SC) {
        // commit prefetched chunk to smem
        #pragma unroll
        for (int e = 0; e < 4; ++e) {
            const float qe = (&qv.x)[e];
            Qs[(sl+e)*QSS + 2*lsub    ] = qe;
            Qs[(sl+e)*QSS + 2*lsub + 1] = qe;
        }
        #pragma unroll
        for (int g = 0; g < 8; ++g) if (g < ngrp) {
            #pragma unroll
            for (int e = 0; e < 4; ++e)
                Ks[(sl+e)*KSS + lsub + 32*g] = (&kv[g].x)[e];
        }
        __syncthreads();

        // prefetch next chunk (in flight during compute)
        const int s1 = s0 + SC;
        if (s1 < SS) {
            const int off = (s1 >> 7)*NSTRIDE + (s1 & 127);
            qv = *(const float4*)(q + qbase + off);
            #pragma unroll
            for (int g = 0; g < 8; ++g) if (g < ngrp)
                kv[g] = *(const float4*)(k + kbase[g] + off);
        }

        #pragma unroll 8
        for (int s = 0; s < SC; ++s) {
            const ull qp0 = *(const ull*)&Qs[s*QSS + 2*rloc0    ];
            const ull qp1 = *(const ull*)&Qs[s*QSS + 2*rloc0 + 2];
            const ull qp2 = *(const ull*)&Qs[s*QSS + 2*rloc0 + 4];
            const ull qp3 = *(const ull*)&Qs[s*QSS + 2*rloc0 + 6];
            #pragma unroll
            for (int jj = 0; jj < 4; ++jj) if (jj < njj) {
                const ull kp = *(const ull*)&Ks[s*KSS + 64*jj + 2*tx];
                ffma2(acc[0][jj], qp0, kp);
                ffma2(acc[1][jj], qp1, kp);
                ffma2(acc[2][jj], qp2, kp);
                ffma2(acc[3][jj], qp3, kp);
            }
        }
        __syncthreads();
    }

    // epilogue: scale, causal mask, softmax (row fully inside one warp)
    const int bb = b*CH;
    float ikA[4], ikB[4];
    #pragma unroll
    for (int jj = 0; jj < 4; ++jj) if (jj < njj) {
        ikA[jj] = g_invk[bb + 64*jj + 2*tx    ];
        ikB[jj] = g_invk[bb + 64*jj + 2*tx + 1];
    }
    #pragma unroll
    for (int i = 0; i < 4; ++i) {
        const int trow = rabs0 + i;
        const float iq = g_invq[bb + trow];
        float v0[4], v1[4], e0[4], e1[4];
        float m = -1e30f;
        #pragma unroll
        for (int jj = 0; jj < 4; ++jj) if (jj < njj) {
            float a, c; unpack2(acc[i][jj], a, c);
            const int col = 64*jj + 2*tx;
            v0[jj] = (col     <= trow) ? a*iq*ikA[jj] : -1e30f;
            v1[jj] = (col + 1 <= trow) ? c*iq*ikB[jj] : -1e30f;
            m = fmaxf(m, fmaxf(v0[jj], v1[jj]));
        }
        #pragma unroll
        for (int o = 16; o; o >>= 1) m = fmaxf(m, __shfl_xor_sync(0xffffffffu, m, o));
        float ssum = 0.f;
        #pragma unroll
        for (int jj = 0; jj < 4; ++jj) if (jj < njj) {
            const int col = 64*jj + 2*tx;
            e0[jj] = (col     <= trow) ? __expf(v0[jj] - m) : 0.f;
            e1[jj] = (col + 1 <= trow) ? __expf(v1[jj] - m) : 0.f;
            ssum += e0[jj] + e1[jj];
        }
        #pragma unroll
        for (int o = 16; o; o >>= 1) ssum += __shfl_xor_sync(0xffffffffu, ssum, o);
        const float inv = 1.f/ssum;
        #pragma unroll
        for (int jj = 0; jj < 4; ++jj) if (jj < njj)
            *(ull*)&g_p[(bb + trow)*CH + 64*jj + 2*tx] = pack2(e0[jj]*inv, e1[jj]*inv);
    }
}

// ---------------------------------------------------------------------------
// Kernel 3: out = P @ V + token_v, packed f32x2, causal r-bound.
// CTA = 32(t) x 128(w) tile for one (b, tt, n). 3200 CTAs (many waves ->
// causal imbalance amortizes). P duplicated-broadcast in smem.
// ---------------------------------------------------------------------------
#define PSS 68
__global__ __launch_bounds__(256) void out_kernel(const float* __restrict__ v,
                                                  float* __restrict__ out) {
    __shared__ __align__(16) float Ps[32*PSS];   // [r][2*t] duplicated P
    __shared__ __align__(16) float Vs[32*WW];    // [r][w]
    const int n   = blockIdx.x % NN;
    const int tmp = blockIdx.x / NN;
    const int tt  = tmp & 7, b = tmp >> 3;
    const int t0  = tt*32;
    const int tid = threadIdx.x, tx = tid & 31, ty = tid >> 5;
    const int bb  = b*CH;
    const int tl  = tid >> 3, rq4 = (tid & 7)*4;
    const int nr  = 32*(tt + 1);                 // causal bound on r

    ull acc[4][2];
    #pragma unroll
    for (int i = 0; i < 4; ++i) { acc[i][0] = 0ull; acc[i][1] = 0ull; }

    const int prow = (bb + t0 + tl)*CH + rq4;

    // prefetch chunk 0
    float4 pv = *(const float4*)&g_p[prow];
    float4 vv4[4];
    {
        const int gv = row_base(b, tl) + n*NSTRIDE;
        #pragma unroll
        for (int g = 0; g < 4; ++g)
            vv4[g] = *(const float4*)(v + gv + rq4 + 32*g);
    }

    for (int rc0 = 0; rc0 < nr; rc0 += 32) {
        #pragma unroll
        for (int e = 0; e < 4; ++e) {
            const float pe = (&pv.x)[e];
            Ps[(rq4+e)*PSS + 2*tl    ] = pe;
            Ps[(rq4+e)*PSS + 2*tl + 1] = pe;
        }
        #pragma unroll
        for (int g = 0; g < 4; ++g)
            *(float4*)&Vs[tl*WW + rq4 + 32*g] = vv4[g];
        __syncthreads();

        const int rc1 = rc0 + 32;
        if (rc1 < nr) {
            pv = *(const float4*)&g_p[prow + rc1];
            const int gv = row_base(b, rc1 + tl) + n*NSTRIDE;
            #pragma unroll
            for (int g = 0; g < 4; ++g)
                vv4[g] = *(const float4*)(v + gv + rq4 + 32*g);
        }

        #pragma unroll 8
        for (int r = 0; r < 32; ++r) {
            const ulonglong2 pp01 = *(const ulonglong2*)&Ps[r*PSS + 8*ty    ];
            const ulonglong2 pp23 = *(const ulonglong2*)&Ps[r*PSS + 8*ty + 4];
            const ulonglong2 vv   = *(const ulonglong2*)&Vs[r*WW + tx*4];
            ffma2(acc[0][0], pp01.x, vv.x); ffma2(acc[0][1], pp01.x, vv.y);
            ffma2(acc[1][0], pp01.y, vv.x); ffma2(acc[1][1], pp01.y, vv.y);
            ffma2(acc[2][0], pp23.x, vv.x); ffma2(acc[2][1], pp23.x, vv.y);
            ffma2(acc[3][0], pp23.y, vv.x); ffma2(acc[3][1], pp23.y, vv.y);
        }
        __syncthreads();
    }

    #pragma unroll
    for (int i = 0; i < 4; ++i) {
        const int t = t0 + ty*4 + i;
        const int a = row_base(b, t) + n*NSTRIDE + tx*4;
        const float4 bu = *(const float4*)(v + a);
        float o0, o1, o2, o3;
        unpack2(acc[i][0], o0, o1);
        unpack2(acc[i][1], o2, o3);
        const float4 o = make_float4(o0 + bu.x, o1 + bu.y, o2 + bu.z, o3 + bu.w);
        *(float4*)(out + a) = o;
    }
}

// ---------------------------------------------------------------------------
extern "C" void kernel_launch(void* const* d_in, const int* in_sizes, int n_in,
                              void* d_out, int out_size) {
    const float* q = (const float*)d_in[0];
    const float* k = (const float*)d_in[1];
    const float* v = (const float*)d_in[2];
    float* out = (float*)d_out;

    norms_kernel<<<BB*CH/8, 256>>>(q, k);
    att_kernel<<<BB*8, 256>>>(q, k);
    out_kernel<<<BB*8*NN, 256>>>(v, out);
}